// round 2
// baseline (speedup 1.0000x reference)
#include <cuda_runtime.h>
#include <cuda_bf16.h>
#include <cstdint>

#define NNODES 100000
#define NEDGES 800000
#define DIM 128

// ---------------- static scratch (no allocations allowed) ----------------
__device__ __align__(16) float g_agg[(size_t)NNODES * DIM];
__device__ __align__(16) float g_z[(size_t)NNODES * DIM];
__device__ __align__(16) float g_h[(size_t)NNODES * DIM];
__device__ __align__(16) __nv_bfloat16 g_as[(size_t)NNODES * 2 * DIM];  // [N][256] hi|lo
__device__ __align__(16) __nv_bfloat16 g_ts[(size_t)NNODES * 2 * DIM];  // [N][256] hi|lo
__device__ __align__(16) __nv_bfloat16 g_wt[6 * 128 * 256];             // [l*2+m][n][256] hi|lo
__device__ float g_stats[256];  // colsum[128], colsumsq[128]
__device__ int g_deg[NNODES];
__device__ int g_rowptr[NNODES];
__device__ int g_cursor[NNODES];
__device__ int g_eidx[NEDGES];
__device__ int g_part[512];
__device__ int g_is64;

// ---------------- dtype detection for edge_index (jax x64 trap) ----------------
// If the reference ran with default JAX config, edge_index is int32 despite the
// declared int64. Reading the first entries as int64: genuine int64 data gives
// values in [0, n); int32 data read as int64 packs the next index into the high
// word -> out of range. Deterministic, runs every call.
__global__ void detect_kernel(const void* __restrict__ ei, int E, int n) {
    __shared__ int bad;
    if (threadIdx.x == 0) bad = 0;
    __syncthreads();
    const long long* p = (const long long*)ei;
    int m = (E < 4096) ? E : 4096;  // first E int64 slots always within buffer
    for (int i = threadIdx.x; i < m; i += blockDim.x) {
        long long v = p[i];
        if (v < 0 || v >= (long long)n) bad = 1;
    }
    __syncthreads();
    if (threadIdx.x == 0) g_is64 = bad ? 0 : 1;
}

__device__ __forceinline__ int load_idx(const void* ei, int is64, size_t pos) {
    if (is64) return (int)((const long long*)ei)[pos];
    return ((const int*)ei)[pos];
}

// ---------------- weight prep: transpose + hi/lo bf16 split ----------------
__global__ void wprep_kernel(const float* __restrict__ W1, const float* __restrict__ W2) {
    int idx = blockIdx.x * blockDim.x + threadIdx.x;
    if (idx >= 3 * 2 * 128 * 128) return;
    int n = idx & 127;
    int k = (idx >> 7) & 127;
    int m = (idx >> 14) & 1;
    int l = idx >> 15;
    const float* W = m ? W2 : W1;
    float v = W[((size_t)l * 128 + k) * 128 + n];
    __nv_bfloat16 hi = __float2bfloat16(v);
    __nv_bfloat16 lo = __float2bfloat16(v - __bfloat162float(hi));
    size_t base = ((size_t)(l * 2 + m) * 128 + n) * 256;
    g_wt[base + k] = hi;
    g_wt[base + 128 + k] = lo;
}

// ---------------- CSR build ----------------
__global__ void zerodeg_kernel(int n) {
    int i = blockIdx.x * blockDim.x + threadIdx.x;
    if (i < n) g_deg[i] = 0;
}

__global__ void hist_kernel(const void* __restrict__ ei, int E, int n) {
    int e = blockIdx.x * blockDim.x + threadIdx.x;
    if (e >= E) return;
    int d = load_idx(ei, g_is64, (size_t)E + e);
    if ((unsigned)d < (unsigned)n) atomicAdd(&g_deg[d], 1);
}

__global__ void scanA_kernel(int n) {
    __shared__ int s[512];
    int tid = threadIdx.x;
    int i = blockIdx.x * 512 + tid;
    s[tid] = (i < n) ? g_deg[i] : 0;
    __syncthreads();
    for (int off = 256; off > 0; off >>= 1) {
        if (tid < off) s[tid] += s[tid + off];
        __syncthreads();
    }
    if (tid == 0) g_part[blockIdx.x] = s[0];
}

__global__ void scanB_kernel(int nb) {
    if (threadIdx.x == 0) {
        int acc = 0;
        for (int i = 0; i < nb; i++) { int t = g_part[i]; g_part[i] = acc; acc += t; }
    }
}

__global__ void scanC_kernel(int n) {
    __shared__ int s[512];
    int tid = threadIdx.x;
    int i = blockIdx.x * 512 + tid;
    int v = (i < n) ? g_deg[i] : 0;
    s[tid] = v;
    __syncthreads();
    for (int off = 1; off < 512; off <<= 1) {
        int tv = (tid >= off) ? s[tid - off] : 0;
        __syncthreads();
        s[tid] += tv;
        __syncthreads();
    }
    if (i < n) {
        int start = g_part[blockIdx.x] + s[tid] - v;
        g_rowptr[i] = start;
        g_cursor[i] = start;
    }
}

__global__ void fill_kernel(const void* __restrict__ ei, int E, int n) {
    int e = blockIdx.x * blockDim.x + threadIdx.x;
    if (e >= E) return;
    int is64 = g_is64;
    int s = load_idx(ei, is64, (size_t)e);
    int d = load_idx(ei, is64, (size_t)E + e);
    if ((unsigned)d >= (unsigned)n || (unsigned)s >= (unsigned)n) return;
    int pos = atomicAdd(&g_cursor[d], 1);
    g_eidx[pos] = s;
}

// ---------------- GIN aggregation: agg = h + sum_{in-neighbors} h[src] ----------------
__global__ void gather_kernel(const float* __restrict__ x, int useX, int n) {
    if (blockIdx.x == 0 && threadIdx.x < 256) g_stats[threadIdx.x] = 0.f;  // zero stats
    int gidx = blockIdx.x * blockDim.x + threadIdx.x;
    int node = gidx >> 5;
    if (node >= n) return;
    int lane = gidx & 31;
    const float* h = useX ? x : g_h;
    float4 acc = *reinterpret_cast<const float4*>(h + (size_t)node * DIM + lane * 4);
    int start = g_rowptr[node];
    int cnt = g_deg[node];
    for (int j = 0; j < cnt; j++) {
        int s = g_eidx[start + j];
        float4 v = *reinterpret_cast<const float4*>(h + (size_t)s * DIM + lane * 4);
        acc.x += v.x; acc.y += v.y; acc.z += v.z; acc.w += v.w;
    }
    *reinterpret_cast<float4*>(g_agg + (size_t)node * DIM + lane * 4) = acc;
}

// ---------------- split agg fp32 -> [hi|lo] bf16 ----------------
__global__ void split_kernel(int n) {
    int idx = blockIdx.x * blockDim.x + threadIdx.x;  // one float4 each
    if (idx >= n * 32) return;
    int row = idx >> 5;
    int c4 = (idx & 31) * 4;
    float4 v = *reinterpret_cast<const float4*>(g_agg + (size_t)row * DIM + c4);
    float vv[4] = {v.x, v.y, v.z, v.w};
    __nv_bfloat16 hi[4], lo[4];
#pragma unroll
    for (int j = 0; j < 4; j++) {
        hi[j] = __float2bfloat16(vv[j]);
        lo[j] = __float2bfloat16(vv[j] - __bfloat162float(hi[j]));
    }
    __nv_bfloat16* basep = g_as + (size_t)row * 256 + c4;
    __nv_bfloat162 h01; h01.x = hi[0]; h01.y = hi[1];
    __nv_bfloat162 h23; h23.x = hi[2]; h23.y = hi[3];
    __nv_bfloat162 l01; l01.x = lo[0]; l01.y = lo[1];
    __nv_bfloat162 l23; l23.x = lo[2]; l23.y = lo[3];
    *reinterpret_cast<__nv_bfloat162*>(basep + 0) = h01;
    *reinterpret_cast<__nv_bfloat162*>(basep + 2) = h23;
    *reinterpret_cast<__nv_bfloat162*>(basep + 128 + 0) = l01;
    *reinterpret_cast<__nv_bfloat162*>(basep + 128 + 2) = l23;
}

// ---------------- GEMM: [N,128(+lo)] @ [128,128] via mma.sync bf16 hi/lo split ----------------
#define ASTRIDE 264
#define SMEM_BYTES (2 * 128 * ASTRIDE * 2)

__device__ __forceinline__ void mma_bf16(float d[4], const uint32_t a[4], const uint32_t b[2]) {
    asm volatile(
        "mma.sync.aligned.m16n8k16.row.col.f32.bf16.bf16.f32 "
        "{%0,%1,%2,%3}, {%4,%5,%6,%7}, {%8,%9}, {%0,%1,%2,%3};\n"
        : "+f"(d[0]), "+f"(d[1]), "+f"(d[2]), "+f"(d[3])
        : "r"(a[0]), "r"(a[1]), "r"(a[2]), "r"(a[3]), "r"(b[0]), "r"(b[1]));
}

template <int MODE>
__global__ __launch_bounds__(256) void gemm_kernel(int wmat, const float* __restrict__ bias, int n) {
    extern __shared__ char smem_raw[];
    __nv_bfloat16* As = reinterpret_cast<__nv_bfloat16*>(smem_raw);
    __nv_bfloat16* Bs = As + 128 * ASTRIDE;

    const __nv_bfloat16* __restrict__ Ag = (MODE == 0) ? g_as : g_ts;
    const __nv_bfloat16* __restrict__ Bg = g_wt + (size_t)wmat * 128 * 256;

    int tid = threadIdx.x;
    int rowBase = blockIdx.x * 128;

    for (int i = tid; i < 4096; i += 256) {
        int r = i >> 5, s = i & 31;
        uint4 av = make_uint4(0u, 0u, 0u, 0u);
        int row = rowBase + r;
        if (row < n) av = *reinterpret_cast<const uint4*>(Ag + (size_t)row * 256 + s * 8);
        *reinterpret_cast<uint4*>(As + r * ASTRIDE + s * 8) = av;
        uint4 bv = *reinterpret_cast<const uint4*>(Bg + (size_t)r * 256 + s * 8);
        *reinterpret_cast<uint4*>(Bs + r * ASTRIDE + s * 8) = bv;
    }
    __syncthreads();

    int warp = tid >> 5, lane = tid & 31;
    int wm = warp & 1, wn = warp >> 1;
    int mBase = wm * 64, nBase = wn * 32;
    int g = lane >> 2, t = lane & 3;

    float acc[4][4][4];
#pragma unroll
    for (int a = 0; a < 4; a++)
#pragma unroll
        for (int b = 0; b < 4; b++)
#pragma unroll
            for (int c = 0; c < 4; c++) acc[a][b][c] = 0.f;

    const int aOffs[3] = {0, 0, 128};
    const int bOffs[3] = {0, 128, 0};
#pragma unroll
    for (int p = 0; p < 3; p++) {
        int aO = aOffs[p], bO = bOffs[p];
#pragma unroll
        for (int kk = 0; kk < 128; kk += 16) {
            uint32_t afr[4][4], bfr[4][2];
#pragma unroll
            for (int mt = 0; mt < 4; mt++) {
                const __nv_bfloat16* ap = As + (mBase + mt * 16 + g) * ASTRIDE + aO + kk + t * 2;
                afr[mt][0] = *reinterpret_cast<const uint32_t*>(ap);
                afr[mt][1] = *reinterpret_cast<const uint32_t*>(ap + 8 * ASTRIDE);
                afr[mt][2] = *reinterpret_cast<const uint32_t*>(ap + 8);
                afr[mt][3] = *reinterpret_cast<const uint32_t*>(ap + 8 * ASTRIDE + 8);
            }
#pragma unroll
            for (int nt = 0; nt < 4; nt++) {
                const __nv_bfloat16* bp = Bs + (nBase + nt * 8 + g) * ASTRIDE + bO + kk + t * 2;
                bfr[nt][0] = *reinterpret_cast<const uint32_t*>(bp);
                bfr[nt][1] = *reinterpret_cast<const uint32_t*>(bp + 8);
            }
#pragma unroll
            for (int mt = 0; mt < 4; mt++)
#pragma unroll
                for (int nt = 0; nt < 4; nt++) mma_bf16(acc[mt][nt], afr[mt], bfr[nt]);
        }
    }

    if (MODE == 0) {
#pragma unroll
        for (int mt = 0; mt < 4; mt++) {
#pragma unroll
            for (int i = 0; i < 2; i++) {
                int row = rowBase + mBase + mt * 16 + g + i * 8;
                if (row >= n) continue;
#pragma unroll
                for (int nt = 0; nt < 4; nt++) {
                    int col = nBase + nt * 8 + t * 2;
                    float v0 = fmaxf(acc[mt][nt][i * 2 + 0] + bias[col], 0.f);
                    float v1 = fmaxf(acc[mt][nt][i * 2 + 1] + bias[col + 1], 0.f);
                    __nv_bfloat16 h0 = __float2bfloat16(v0);
                    __nv_bfloat16 h1 = __float2bfloat16(v1);
                    __nv_bfloat16 l0 = __float2bfloat16(v0 - __bfloat162float(h0));
                    __nv_bfloat16 l1 = __float2bfloat16(v1 - __bfloat162float(h1));
                    __nv_bfloat162 hp; hp.x = h0; hp.y = h1;
                    __nv_bfloat162 lp; lp.x = l0; lp.y = l1;
                    __nv_bfloat16* op = g_ts + (size_t)row * 256 + col;
                    *reinterpret_cast<__nv_bfloat162*>(op) = hp;
                    *reinterpret_cast<__nv_bfloat162*>(op + 128) = lp;
                }
            }
        }
    } else {
        float* ssum = reinterpret_cast<float*>(smem_raw);
        float* ssq = ssum + 128;
        __syncthreads();
        if (tid < 128) { ssum[tid] = 0.f; ssq[tid] = 0.f; }
        __syncthreads();
        float cs[4][2], cq[4][2];
#pragma unroll
        for (int nt = 0; nt < 4; nt++) { cs[nt][0] = cs[nt][1] = 0.f; cq[nt][0] = cq[nt][1] = 0.f; }
#pragma unroll
        for (int mt = 0; mt < 4; mt++) {
#pragma unroll
            for (int i = 0; i < 2; i++) {
                int row = rowBase + mBase + mt * 16 + g + i * 8;
                if (row >= n) continue;
#pragma unroll
                for (int nt = 0; nt < 4; nt++) {
                    int col = nBase + nt * 8 + t * 2;
                    float v0 = acc[mt][nt][i * 2 + 0] + bias[col];
                    float v1 = acc[mt][nt][i * 2 + 1] + bias[col + 1];
                    float2 zv; zv.x = v0; zv.y = v1;
                    *reinterpret_cast<float2*>(g_z + (size_t)row * DIM + col) = zv;
                    cs[nt][0] += v0; cq[nt][0] += v0 * v0;
                    cs[nt][1] += v1; cq[nt][1] += v1 * v1;
                }
            }
        }
#pragma unroll
        for (int nt = 0; nt < 4; nt++) {
#pragma unroll
            for (int j = 0; j < 2; j++) {
                int col = nBase + nt * 8 + t * 2 + j;
                atomicAdd(&ssum[col], cs[nt][j]);
                atomicAdd(&ssq[col], cq[nt][j]);
            }
        }
        __syncthreads();
        if (tid < 128) {
            atomicAdd(&g_stats[tid], ssum[tid]);
            atomicAdd(&g_stats[128 + tid], ssq[tid]);
        }
    }
}

// ---------------- BatchNorm (batch stats) + ReLU ----------------
__global__ void bnrelu_kernel(const float* __restrict__ gamma, const float* __restrict__ beta,
                              float* __restrict__ dout, int last, int n) {
    int idx = blockIdx.x * blockDim.x + threadIdx.x;
    if (idx >= n * 32) return;
    int row = idx >> 5;
    int c4 = (idx & 31) * 4;
    float4 z = *reinterpret_cast<const float4*>(g_z + (size_t)row * DIM + c4);
    float zz[4] = {z.x, z.y, z.z, z.w};
    float out[4];
    float invN = 1.f / (float)n;
#pragma unroll
    for (int j = 0; j < 4; j++) {
        int c = c4 + j;
        float mean = g_stats[c] * invN;
        float var = g_stats[128 + c] * invN - mean * mean;
        float rstd = rsqrtf(fmaxf(var, 0.f) + 1e-5f);
        out[j] = fmaxf(gamma[c] * (zz[j] - mean) * rstd + beta[c], 0.f);
    }
    float* op = (last ? dout : g_h) + (size_t)row * DIM + c4;
    float4 o; o.x = out[0]; o.y = out[1]; o.z = out[2]; o.w = out[3];
    *reinterpret_cast<float4*>(op) = o;
}

// ---------------- host launcher ----------------
extern "C" void kernel_launch(void* const* d_in, const int* in_sizes, int n_in,
                              void* d_out, int out_size) {
    const float* x = (const float*)d_in[0];
    const void* ei = d_in[1];
    const float* W1 = (const float*)d_in[2];
    const float* b1 = (const float*)d_in[3];
    const float* W2 = (const float*)d_in[4];
    const float* b2 = (const float*)d_in[5];
    const float* gamma = (const float*)d_in[6];
    const float* beta = (const float*)d_in[7];
    (void)n_in; (void)out_size;

    int n = in_sizes[0] / DIM;
    int E = in_sizes[1] / 2;
    if (n > NNODES) n = NNODES;
    if (E > NEDGES) E = NEDGES;

    cudaFuncSetAttribute(gemm_kernel<0>, cudaFuncAttributeMaxDynamicSharedMemorySize, SMEM_BYTES);
    cudaFuncSetAttribute(gemm_kernel<1>, cudaFuncAttributeMaxDynamicSharedMemorySize, SMEM_BYTES);

    detect_kernel<<<1, 256>>>(ei, E, n);
    wprep_kernel<<<(3 * 2 * 128 * 128 + 255) / 256, 256>>>(W1, W2);
    zerodeg_kernel<<<(n + 255) / 256, 256>>>(n);
    hist_kernel<<<(E + 255) / 256, 256>>>(ei, E, n);
    int nsb = (n + 511) / 512;
    scanA_kernel<<<nsb, 512>>>(n);
    scanB_kernel<<<1, 32>>>(nsb);
    scanC_kernel<<<nsb, 512>>>(n);
    fill_kernel<<<(E + 255) / 256, 256>>>(ei, E, n);

    int gemmBlocks = (n + 127) / 128;
    int ewBlocks = (n * 32 + 255) / 256;
    for (int l = 0; l < 3; l++) {
        gather_kernel<<<ewBlocks, 256>>>(x, (l == 0) ? 1 : 0, n);
        split_kernel<<<ewBlocks, 256>>>(n);
        gemm_kernel<0><<<gemmBlocks, 256, SMEM_BYTES>>>(l * 2 + 0, b1 + l * 128, n);
        gemm_kernel<1><<<gemmBlocks, 256, SMEM_BYTES>>>(l * 2 + 1, b2 + l * 128, n);
        bnrelu_kernel<<<ewBlocks, 256>>>(gamma + l * 128, beta + l * 128,
                                         (float*)d_out, (l == 2) ? 1 : 0, n);
    }
}

// round 4
// speedup vs baseline: 1.0462x; 1.0462x over previous
#include <cuda_runtime.h>
#include <cuda_bf16.h>
#include <cstdint>

#define NNODES 100000
#define NEDGES 800000
#define DIM 128

// ---------------- static scratch (no allocations allowed) ----------------
__device__ __align__(16) float g_z[(size_t)NNODES * DIM];
__device__ __align__(16) __nv_bfloat16 g_as[(size_t)NNODES * 2 * DIM];  // [N][256] hi|lo
__device__ __align__(16) __nv_bfloat16 g_wt[6 * 128 * 256];             // [l*2+m][n][256] hi|lo
__device__ float g_stats[256];      // colsum[128], colsumsq[128]; zeroed by finalize
__device__ float g_bnScale[128];
__device__ float g_bnShift[128];
__device__ int g_deg[NNODES];
__device__ int g_rowptr[NNODES];
__device__ int g_cursor[NNODES];
__device__ int g_eidx[NEDGES];
__device__ int g_part[512];
__device__ int g_is64;

// ---------------- dtype detection for edge_index (jax x64 trap) ----------------
__global__ void detect_kernel(const void* __restrict__ ei, int E, int n) {
    __shared__ int bad;
    if (threadIdx.x == 0) bad = 0;
    __syncthreads();
    const long long* p = (const long long*)ei;
    int m = (E < 4096) ? E : 4096;
    for (int i = threadIdx.x; i < m; i += blockDim.x) {
        long long v = p[i];
        if (v < 0 || v >= (long long)n) bad = 1;
    }
    __syncthreads();
    if (threadIdx.x == 0) g_is64 = bad ? 0 : 1;
}

__device__ __forceinline__ int load_idx(const void* ei, int is64, size_t pos) {
    if (is64) return (int)((const long long*)ei)[pos];
    return ((const int*)ei)[pos];
}

// ---------------- weight prep: transpose + hi/lo bf16 split ----------------
__global__ void wprep_kernel(const float* __restrict__ W1, const float* __restrict__ W2) {
    int idx = blockIdx.x * blockDim.x + threadIdx.x;
    if (idx >= 3 * 2 * 128 * 128) return;
    int n = idx & 127;
    int k = (idx >> 7) & 127;
    int m = (idx >> 14) & 1;
    int l = idx >> 15;
    const float* W = m ? W2 : W1;
    float v = W[((size_t)l * 128 + k) * 128 + n];
    __nv_bfloat16 hi = __float2bfloat16(v);
    __nv_bfloat16 lo = __float2bfloat16(v - __bfloat162float(hi));
    size_t base = ((size_t)(l * 2 + m) * 128 + n) * 256;
    g_wt[base + k] = hi;
    g_wt[base + 128 + k] = lo;
}

// ---------------- CSR build ----------------
__global__ void zerodeg_kernel(int n) {
    int i = blockIdx.x * blockDim.x + threadIdx.x;
    if (i < n) g_deg[i] = 0;
}

__global__ void hist_kernel(const void* __restrict__ ei, int E, int n) {
    int e = blockIdx.x * blockDim.x + threadIdx.x;
    if (e >= E) return;
    int d = load_idx(ei, g_is64, (size_t)E + e);
    if ((unsigned)d < (unsigned)n) atomicAdd(&g_deg[d], 1);
}

__global__ void scanA_kernel(int n) {
    __shared__ int s[512];
    int tid = threadIdx.x;
    int i = blockIdx.x * 512 + tid;
    s[tid] = (i < n) ? g_deg[i] : 0;
    __syncthreads();
    for (int off = 256; off > 0; off >>= 1) {
        if (tid < off) s[tid] += s[tid + off];
        __syncthreads();
    }
    if (tid == 0) g_part[blockIdx.x] = s[0];
}

__global__ void scanB_kernel(int nb) {
    if (threadIdx.x == 0) {
        int acc = 0;
        for (int i = 0; i < nb; i++) { int t = g_part[i]; g_part[i] = acc; acc += t; }
    }
}

__global__ void scanC_kernel(int n) {
    __shared__ int s[512];
    int tid = threadIdx.x;
    int i = blockIdx.x * 512 + tid;
    int v = (i < n) ? g_deg[i] : 0;
    s[tid] = v;
    __syncthreads();
    for (int off = 1; off < 512; off <<= 1) {
        int tv = (tid >= off) ? s[tid - off] : 0;
        __syncthreads();
        s[tid] += tv;
        __syncthreads();
    }
    if (i < n) {
        int start = g_part[blockIdx.x] + s[tid] - v;
        g_rowptr[i] = start;
        g_cursor[i] = start;
    }
}

__global__ void fill_kernel(const void* __restrict__ ei, int E, int n) {
    int e = blockIdx.x * blockDim.x + threadIdx.x;
    if (e >= E) return;
    int is64 = g_is64;
    int s = load_idx(ei, is64, (size_t)e);
    int d = load_idx(ei, is64, (size_t)E + e);
    if ((unsigned)d >= (unsigned)n || (unsigned)s >= (unsigned)n) return;
    int pos = atomicAdd(&g_cursor[d], 1);
    g_eidx[pos] = s;
}

// ---------------- fused gather: (optional BN+ReLU) + aggregate + hi/lo split ----------------
// BN==0: source = xparam (raw input). BN==1: source = g_z (device symbol, resolved
// IN KERNEL -- passing a __device__ symbol from host code was the Round-3 bug).
template <int BN>
__global__ void gather_kernel(const float* __restrict__ xparam, int n) {
    int gidx = blockIdx.x * blockDim.x + threadIdx.x;
    int node = gidx >> 5;
    if (node >= n) return;
    int lane = gidx & 31;
    int c4 = lane * 4;

    const float* __restrict__ hsrc = BN ? (const float*)g_z : xparam;

    float4 sc, sh;
    if (BN) {
        sc = *reinterpret_cast<const float4*>(g_bnScale + c4);
        sh = *reinterpret_cast<const float4*>(g_bnShift + c4);
    }

    float4 v = *reinterpret_cast<const float4*>(hsrc + (size_t)node * DIM + c4);
    float ax, ay, az, aw;
    if (BN) {
        ax = fmaxf(v.x * sc.x + sh.x, 0.f);
        ay = fmaxf(v.y * sc.y + sh.y, 0.f);
        az = fmaxf(v.z * sc.z + sh.z, 0.f);
        aw = fmaxf(v.w * sc.w + sh.w, 0.f);
    } else {
        ax = v.x; ay = v.y; az = v.z; aw = v.w;
    }

    int start = g_rowptr[node];
    int cnt = g_deg[node];
    for (int j = 0; j < cnt; j++) {
        int s = g_eidx[start + j];
        float4 u = *reinterpret_cast<const float4*>(hsrc + (size_t)s * DIM + c4);
        if (BN) {
            ax += fmaxf(u.x * sc.x + sh.x, 0.f);
            ay += fmaxf(u.y * sc.y + sh.y, 0.f);
            az += fmaxf(u.z * sc.z + sh.z, 0.f);
            aw += fmaxf(u.w * sc.w + sh.w, 0.f);
        } else {
            ax += u.x; ay += u.y; az += u.z; aw += u.w;
        }
    }

    // hi/lo split -> g_as
    float vv[4] = {ax, ay, az, aw};
    __nv_bfloat16 hi[4], lo[4];
#pragma unroll
    for (int j = 0; j < 4; j++) {
        hi[j] = __float2bfloat16(vv[j]);
        lo[j] = __float2bfloat16(vv[j] - __bfloat162float(hi[j]));
    }
    union { __nv_bfloat162 b2[2]; uint2 u; } H, L;
    H.b2[0].x = hi[0]; H.b2[0].y = hi[1]; H.b2[1].x = hi[2]; H.b2[1].y = hi[3];
    L.b2[0].x = lo[0]; L.b2[0].y = lo[1]; L.b2[1].x = lo[2]; L.b2[1].y = lo[3];
    __nv_bfloat16* op = g_as + (size_t)node * 256 + c4;
    *reinterpret_cast<uint2*>(op) = H.u;
    *reinterpret_cast<uint2*>(op + 128) = L.u;
}

// ---------------- fused MLP: agg -> W1+bias+relu (smem) -> W2+bias -> g_z + stats ----------------
#define ASTRIDE 264
#define SMEM_BYTES (2 * 128 * ASTRIDE * 2)

__device__ __forceinline__ void mma_bf16(float d[4], const uint32_t a[4], const uint32_t b0, const uint32_t b1) {
    asm volatile(
        "mma.sync.aligned.m16n8k16.row.col.f32.bf16.bf16.f32 "
        "{%0,%1,%2,%3}, {%4,%5,%6,%7}, {%8,%9}, {%0,%1,%2,%3};\n"
        : "+f"(d[0]), "+f"(d[1]), "+f"(d[2]), "+f"(d[3])
        : "r"(a[0]), "r"(a[1]), "r"(a[2]), "r"(a[3]), "r"(b0), "r"(b1));
}

__device__ __forceinline__ void ldsm_x4(uint32_t r[4], uint32_t addr) {
    asm volatile("ldmatrix.sync.aligned.m8n8.x4.shared.b16 {%0,%1,%2,%3}, [%4];\n"
                 : "=r"(r[0]), "=r"(r[1]), "=r"(r[2]), "=r"(r[3]) : "r"(addr));
}

__device__ __forceinline__ void cpa16(uint32_t dst, const void* src) {
    asm volatile("cp.async.ca.shared.global [%0], [%1], 16;\n" :: "r"(dst), "l"(src));
}
__device__ __forceinline__ void cpa_commit_wait() {
    asm volatile("cp.async.commit_group;\n");
    asm volatile("cp.async.wait_group 0;\n" ::: "memory");
}

// one gemm phase: acc += A(hi/lo 256-wide smem) x B(hi/lo 256-wide smem), 3 passes
__device__ __forceinline__ void gemm_phase(uint32_t aAddr[4], uint32_t bAddr[2], float acc[4][4][4]) {
    const int aOffs[3] = {0, 0, 128};
    const int bOffs[3] = {0, 128, 0};
#pragma unroll
    for (int p = 0; p < 3; p++) {
        int aO = aOffs[p] * 2, bO = bOffs[p] * 2;
#pragma unroll
        for (int kk = 0; kk < 128; kk += 16) {
            uint32_t a[4][4], b[2][4];
#pragma unroll
            for (int mt = 0; mt < 4; mt++) ldsm_x4(a[mt], aAddr[mt] + aO + kk * 2);
#pragma unroll
            for (int np = 0; np < 2; np++) ldsm_x4(b[np], bAddr[np] + bO + kk * 2);
#pragma unroll
            for (int mt = 0; mt < 4; mt++)
#pragma unroll
                for (int nt = 0; nt < 4; nt++)
                    mma_bf16(acc[mt][nt], a[mt], b[nt >> 1][(nt & 1) * 2], b[nt >> 1][(nt & 1) * 2 + 1]);
        }
    }
}

__global__ __launch_bounds__(256) void mlp_kernel(int layer, const float* __restrict__ b1,
                                                  const float* __restrict__ b2, int n) {
    extern __shared__ char smem_raw[];
    __nv_bfloat16* As = reinterpret_cast<__nv_bfloat16*>(smem_raw);
    __nv_bfloat16* Bs = As + 128 * ASTRIDE;
    uint32_t sA = (uint32_t)__cvta_generic_to_shared(As);
    uint32_t sB = (uint32_t)__cvta_generic_to_shared(Bs);

    const __nv_bfloat16* __restrict__ W1g = g_wt + (size_t)(layer * 2 + 0) * 128 * 256;
    const __nv_bfloat16* __restrict__ W2g = g_wt + (size_t)(layer * 2 + 1) * 128 * 256;

    int tid = threadIdx.x;
    int rowBase = blockIdx.x * 128;

    // ---- load A tile + W1 via cp.async ----
    for (int i = tid; i < 4096; i += 256) {
        int r = i >> 5, s = i & 31;
        int row = rowBase + r; if (row >= n) row = 0;  // clamp (junk rows never emitted)
        cpa16(sA + (r * ASTRIDE + s * 8) * 2, g_as + (size_t)row * 256 + s * 8);
        cpa16(sB + (r * ASTRIDE + s * 8) * 2, W1g + (size_t)r * 256 + s * 8);
    }
    cpa_commit_wait();
    __syncthreads();

    int warp = tid >> 5, lane = tid & 31;
    int wm = warp & 1, wn = warp >> 1;
    int mBase = wm * 64, nBase = wn * 32;
    int g = lane >> 2, t = lane & 3;

    // ldmatrix lane addresses
    uint32_t aAddr[4], bAddr[2];
    {
        int r16 = lane & 15, half = lane >> 4;
#pragma unroll
        for (int mt = 0; mt < 4; mt++)
            aAddr[mt] = sA + ((mBase + mt * 16 + r16) * ASTRIDE + half * 8) * 2;
        int q = lane >> 3, rw = lane & 7;
        int rowoff = (q >> 1) * 8 + rw, coloff = (q & 1) * 8;
#pragma unroll
        for (int np = 0; np < 2; np++)
            bAddr[np] = sB + ((nBase + np * 16 + rowoff) * ASTRIDE + coloff) * 2;
    }

    float acc[4][4][4];
#pragma unroll
    for (int a = 0; a < 4; a++)
#pragma unroll
        for (int b = 0; b < 4; b++)
#pragma unroll
            for (int c = 0; c < 4; c++) acc[a][b][c] = 0.f;

    // ---- GEMM 1 ----
    gemm_phase(aAddr, bAddr, acc);
    __syncthreads();  // everyone done reading As/Bs

    // start W2 load (overlaps epilogue-0 smem writes)
    for (int i = tid; i < 4096; i += 256) {
        int r = i >> 5, s = i & 31;
        cpa16(sB + (r * ASTRIDE + s * 8) * 2, W2g + (size_t)r * 256 + s * 8);
    }
    asm volatile("cp.async.commit_group;\n");

    // ---- epilogue 0: bias1 + relu + hi/lo split -> As ----
#pragma unroll
    for (int mt = 0; mt < 4; mt++) {
#pragma unroll
        for (int i = 0; i < 2; i++) {
            int lrow = mBase + mt * 16 + g + i * 8;
#pragma unroll
            for (int nt = 0; nt < 4; nt++) {
                int col = nBase + nt * 8 + t * 2;
                float v0 = fmaxf(acc[mt][nt][i * 2 + 0] + __ldg(b1 + col), 0.f);
                float v1 = fmaxf(acc[mt][nt][i * 2 + 1] + __ldg(b1 + col + 1), 0.f);
                __nv_bfloat16 h0 = __float2bfloat16(v0);
                __nv_bfloat16 h1 = __float2bfloat16(v1);
                __nv_bfloat16 l0 = __float2bfloat16(v0 - __bfloat162float(h0));
                __nv_bfloat16 l1 = __float2bfloat16(v1 - __bfloat162float(h1));
                __nv_bfloat162 hp; hp.x = h0; hp.y = h1;
                __nv_bfloat162 lp; lp.x = l0; lp.y = l1;
                __nv_bfloat16* op = As + lrow * ASTRIDE + col;
                *reinterpret_cast<__nv_bfloat162*>(op) = hp;
                *reinterpret_cast<__nv_bfloat162*>(op + 128) = lp;
            }
        }
    }
    asm volatile("cp.async.wait_group 0;\n" ::: "memory");
    __syncthreads();

#pragma unroll
    for (int a = 0; a < 4; a++)
#pragma unroll
        for (int b = 0; b < 4; b++)
#pragma unroll
            for (int c = 0; c < 4; c++) acc[a][b][c] = 0.f;

    // ---- GEMM 2 ----
    gemm_phase(aAddr, bAddr, acc);

    // ---- epilogue 1: bias2 -> g_z, column sum/sumsq -> g_stats ----
    __syncthreads();  // As/Bs free for stats scratch
    float* ssum = reinterpret_cast<float*>(smem_raw);
    float* ssq = ssum + 128;
    if (tid < 128) { ssum[tid] = 0.f; ssq[tid] = 0.f; }
    __syncthreads();

    float cs[4][2], cq[4][2];
#pragma unroll
    for (int nt = 0; nt < 4; nt++) { cs[nt][0] = cs[nt][1] = 0.f; cq[nt][0] = cq[nt][1] = 0.f; }
#pragma unroll
    for (int mt = 0; mt < 4; mt++) {
#pragma unroll
        for (int i = 0; i < 2; i++) {
            int row = rowBase + mBase + mt * 16 + g + i * 8;
            if (row >= n) continue;
#pragma unroll
            for (int nt = 0; nt < 4; nt++) {
                int col = nBase + nt * 8 + t * 2;
                float v0 = acc[mt][nt][i * 2 + 0] + __ldg(b2 + col);
                float v1 = acc[mt][nt][i * 2 + 1] + __ldg(b2 + col + 1);
                float2 zv; zv.x = v0; zv.y = v1;
                *reinterpret_cast<float2*>(g_z + (size_t)row * DIM + col) = zv;
                cs[nt][0] += v0; cq[nt][0] += v0 * v0;
                cs[nt][1] += v1; cq[nt][1] += v1 * v1;
            }
        }
    }
#pragma unroll
    for (int nt = 0; nt < 4; nt++) {
#pragma unroll
        for (int j = 0; j < 2; j++) {
            int col = nBase + nt * 8 + t * 2 + j;
            atomicAdd(&ssum[col], cs[nt][j]);
            atomicAdd(&ssq[col], cq[nt][j]);
        }
    }
    __syncthreads();
    if (tid < 128) {
        atomicAdd(&g_stats[tid], ssum[tid]);
        atomicAdd(&g_stats[128 + tid], ssq[tid]);
    }
}

// ---------------- stats finalize: scale/shift for BN, then zero stats ----------------
__global__ void finalize_kernel(const float* __restrict__ gamma, const float* __restrict__ beta, int n) {
    int c = threadIdx.x;
    if (c < 128) {
        float invN = 1.f / (float)n;
        float mean = g_stats[c] * invN;
        float var = g_stats[128 + c] * invN - mean * mean;
        float rstd = rsqrtf(fmaxf(var, 0.f) + 1e-5f);
        float scale = gamma[c] * rstd;
        g_bnScale[c] = scale;
        g_bnShift[c] = beta[c] - mean * scale;
        g_stats[c] = 0.f;
        g_stats[128 + c] = 0.f;
    }
}

// ---------------- final BN+ReLU -> d_out ----------------
__global__ void bnfinal_kernel(float* __restrict__ dout, int n) {
    int idx = blockIdx.x * blockDim.x + threadIdx.x;
    if (idx >= n * 32) return;
    int row = idx >> 5;
    int c4 = (idx & 31) * 4;
    float4 z = *reinterpret_cast<const float4*>(g_z + (size_t)row * DIM + c4);
    float4 sc = *reinterpret_cast<const float4*>(g_bnScale + c4);
    float4 sh = *reinterpret_cast<const float4*>(g_bnShift + c4);
    float4 o;
    o.x = fmaxf(z.x * sc.x + sh.x, 0.f);
    o.y = fmaxf(z.y * sc.y + sh.y, 0.f);
    o.z = fmaxf(z.z * sc.z + sh.z, 0.f);
    o.w = fmaxf(z.w * sc.w + sh.w, 0.f);
    *reinterpret_cast<float4*>(dout + (size_t)row * DIM + c4) = o;
}

// ---------------- host launcher ----------------
extern "C" void kernel_launch(void* const* d_in, const int* in_sizes, int n_in,
                              void* d_out, int out_size) {
    const float* x = (const float*)d_in[0];
    const void* ei = d_in[1];
    const float* W1 = (const float*)d_in[2];
    const float* b1 = (const float*)d_in[3];
    const float* W2 = (const float*)d_in[4];
    const float* b2 = (const float*)d_in[5];
    const float* gamma = (const float*)d_in[6];
    const float* beta = (const float*)d_in[7];
    (void)n_in; (void)out_size;

    int n = in_sizes[0] / DIM;
    int E = in_sizes[1] / 2;
    if (n > NNODES) n = NNODES;
    if (E > NEDGES) E = NEDGES;

    cudaFuncSetAttribute(mlp_kernel, cudaFuncAttributeMaxDynamicSharedMemorySize, SMEM_BYTES);

    detect_kernel<<<1, 256>>>(ei, E, n);
    wprep_kernel<<<(3 * 2 * 128 * 128 + 255) / 256, 256>>>(W1, W2);
    zerodeg_kernel<<<(n + 255) / 256, 256>>>(n);
    hist_kernel<<<(E + 255) / 256, 256>>>(ei, E, n);
    int nsb = (n + 511) / 512;
    scanA_kernel<<<nsb, 512>>>(n);
    scanB_kernel<<<1, 32>>>(nsb);
    scanC_kernel<<<nsb, 512>>>(n);
    fill_kernel<<<(E + 255) / 256, 256>>>(ei, E, n);

    int gemmBlocks = (n + 127) / 128;
    int ewBlocks = (n * 32 + 255) / 256;
    for (int l = 0; l < 3; l++) {
        if (l == 0) gather_kernel<0><<<ewBlocks, 256>>>(x, n);
        else gather_kernel<1><<<ewBlocks, 256>>>(nullptr, n);
        mlp_kernel<<<gemmBlocks, 256, SMEM_BYTES>>>(l, b1 + l * 128, b2 + l * 128, n);
        finalize_kernel<<<1, 128>>>(gamma + l * 128, beta + l * 128, n);
    }
    bnfinal_kernel<<<ewBlocks, 256>>>((float*)d_out, n);
}

// round 6
// speedup vs baseline: 1.3799x; 1.3190x over previous
#include <cuda_runtime.h>
#include <cuda_bf16.h>
#include <cstdint>

#define NNODES 100000
#define NEDGES 800000
#define DIM 128

// ---------------- static scratch ----------------
__device__ __align__(16) float g_z[(size_t)NNODES * DIM];
__device__ __align__(16) __nv_bfloat16 g_as[(size_t)NNODES * 2 * DIM];  // [N][256] hi|lo
__device__ __align__(16) __nv_bfloat16 g_wt[6 * 128 * 256];             // [l*2+m][n][256] hi|lo
__device__ float g_stats[256];
__device__ float g_bnScale[128];
__device__ float g_bnShift[128];
__device__ int g_deg[NNODES];
__device__ int g_rowptr[NNODES];
__device__ int g_cursor[NNODES];
__device__ int g_eidx[NEDGES];
__device__ int g_part[512];
__device__ int g_is64;

// ---------------- edge dtype detection (jax x64 trap) ----------------
__global__ void detect_kernel(const void* __restrict__ ei, int E, int n) {
    __shared__ int bad;
    if (threadIdx.x == 0) bad = 0;
    __syncthreads();
    const long long* p = (const long long*)ei;
    int m = (E < 4096) ? E : 4096;
    for (int i = threadIdx.x; i < m; i += blockDim.x) {
        long long v = p[i];
        if (v < 0 || v >= (long long)n) bad = 1;
    }
    __syncthreads();
    if (threadIdx.x == 0) g_is64 = bad ? 0 : 1;
}

__device__ __forceinline__ int load_idx(const void* ei, int is64, size_t pos) {
    if (is64) return (int)((const long long*)ei)[pos];
    return ((const int*)ei)[pos];
}

// ---------------- weight prep ----------------
__global__ void wprep_kernel(const float* __restrict__ W1, const float* __restrict__ W2) {
    int idx = blockIdx.x * blockDim.x + threadIdx.x;
    if (idx >= 3 * 2 * 128 * 128) return;
    int n = idx & 127;
    int k = (idx >> 7) & 127;
    int m = (idx >> 14) & 1;
    int l = idx >> 15;
    const float* W = m ? W2 : W1;
    float v = W[((size_t)l * 128 + k) * 128 + n];
    __nv_bfloat16 hi = __float2bfloat16(v);
    __nv_bfloat16 lo = __float2bfloat16(v - __bfloat162float(hi));
    size_t base = ((size_t)(l * 2 + m) * 128 + n) * 256;
    g_wt[base + k] = hi;
    g_wt[base + 128 + k] = lo;
}

// ---------------- CSR build ----------------
__global__ void zerodeg_kernel(int n) {
    int i = blockIdx.x * blockDim.x + threadIdx.x;
    if (i < n) g_deg[i] = 0;
}

__global__ void hist_kernel(const void* __restrict__ ei, int E, int n) {
    int e = blockIdx.x * blockDim.x + threadIdx.x;
    if (e >= E) return;
    int d = load_idx(ei, g_is64, (size_t)E + e);
    if ((unsigned)d < (unsigned)n) atomicAdd(&g_deg[d], 1);
}

__global__ void scanA_kernel(int n) {
    __shared__ int s[512];
    int tid = threadIdx.x;
    int i = blockIdx.x * 512 + tid;
    s[tid] = (i < n) ? g_deg[i] : 0;
    __syncthreads();
    for (int off = 256; off > 0; off >>= 1) {
        if (tid < off) s[tid] += s[tid + off];
        __syncthreads();
    }
    if (tid == 0) g_part[blockIdx.x] = s[0];
}

__global__ void scanB_kernel(int nb) {
    if (threadIdx.x == 0) {
        int acc = 0;
        for (int i = 0; i < nb; i++) { int t = g_part[i]; g_part[i] = acc; acc += t; }
    }
}

__global__ void scanC_kernel(int n) {
    __shared__ int s[512];
    int tid = threadIdx.x;
    int i = blockIdx.x * 512 + tid;
    int v = (i < n) ? g_deg[i] : 0;
    s[tid] = v;
    __syncthreads();
    for (int off = 1; off < 512; off <<= 1) {
        int tv = (tid >= off) ? s[tid - off] : 0;
        __syncthreads();
        s[tid] += tv;
        __syncthreads();
    }
    if (i < n) {
        int start = g_part[blockIdx.x] + s[tid] - v;
        g_rowptr[i] = start;
        g_cursor[i] = start;
    }
}

__global__ void fill_kernel(const void* __restrict__ ei, int E, int n) {
    int e = blockIdx.x * blockDim.x + threadIdx.x;
    if (e >= E) return;
    int is64 = g_is64;
    int s = load_idx(ei, is64, (size_t)e);
    int d = load_idx(ei, is64, (size_t)E + e);
    if ((unsigned)d >= (unsigned)n || (unsigned)s >= (unsigned)n) return;
    int pos = atomicAdd(&g_cursor[d], 1);
    g_eidx[pos] = s;
}

// ---------------- PROBE: gather-shaped kernel for ncu capture slot (launch idx 3) ----
// Structural clone of gather_kernel with synthetic in-bounds random indices.
// Writes g_z, which mlp_kernel fully overwrites before any consumer reads it ->
// zero effect on output; deterministic output preserved.
__global__ __launch_bounds__(256) void probe_kernel(const float* __restrict__ x, int n) {
    int gidx = blockIdx.x * blockDim.x + threadIdx.x;
    int wid = gidx >> 5;
    int node = wid >> 1;
    if (node >= n) return;
    int half = wid & 1;
    int lane = gidx & 31;
    int col = half * 64 + lane * 2;

    float2 v = *reinterpret_cast<const float2*>(x + (size_t)node * DIM + col);
    float ax = v.x, ay = v.y;
    int base = node * 8;
#pragma unroll
    for (int j = 0; j < 8; j += 4) {
        int s0 = g_eidx[base + j] & 0xFFFF;
        int s1 = g_eidx[base + j + 1] & 0xFFFF;
        int s2 = g_eidx[base + j + 2] & 0xFFFF;
        int s3 = g_eidx[base + j + 3] & 0xFFFF;
        float2 u0 = *reinterpret_cast<const float2*>(x + (size_t)s0 * DIM + col);
        float2 u1 = *reinterpret_cast<const float2*>(x + (size_t)s1 * DIM + col);
        float2 u2 = *reinterpret_cast<const float2*>(x + (size_t)s2 * DIM + col);
        float2 u3 = *reinterpret_cast<const float2*>(x + (size_t)s3 * DIM + col);
        ax += u0.x + u1.x + u2.x + u3.x;
        ay += u0.y + u1.y + u2.y + u3.y;
    }
    float2 o; o.x = ax; o.y = ay;
    *reinterpret_cast<float2*>(g_z + (size_t)node * DIM + col) = o;
}

// ---------------- fused gather: (BN+ReLU) + aggregate + hi/lo split ----------------
// 2 warps per node; each warp handles 64 columns (float2 per lane). 4-edge unroll.
template <int BN>
__global__ __launch_bounds__(256) void gather_kernel(const float* __restrict__ xparam, int n) {
    int gidx = blockIdx.x * blockDim.x + threadIdx.x;
    int wid = gidx >> 5;
    int node = wid >> 1;
    if (node >= n) return;
    int half = wid & 1;
    int lane = gidx & 31;
    int col = half * 64 + lane * 2;

    const float* __restrict__ hsrc = BN ? (const float*)g_z : xparam;

    float2 sc, sh;
    if (BN) {
        sc = *reinterpret_cast<const float2*>(g_bnScale + col);
        sh = *reinterpret_cast<const float2*>(g_bnShift + col);
    }

    float2 v = *reinterpret_cast<const float2*>(hsrc + (size_t)node * DIM + col);
    float ax, ay;
    if (BN) {
        ax = fmaxf(v.x * sc.x + sh.x, 0.f);
        ay = fmaxf(v.y * sc.y + sh.y, 0.f);
    } else {
        ax = v.x; ay = v.y;
    }

    int j = g_rowptr[node];
    int end = j + g_deg[node];
    for (; j + 4 <= end; j += 4) {
        int s0 = g_eidx[j], s1 = g_eidx[j + 1], s2 = g_eidx[j + 2], s3 = g_eidx[j + 3];
        float2 u0 = *reinterpret_cast<const float2*>(hsrc + (size_t)s0 * DIM + col);
        float2 u1 = *reinterpret_cast<const float2*>(hsrc + (size_t)s1 * DIM + col);
        float2 u2 = *reinterpret_cast<const float2*>(hsrc + (size_t)s2 * DIM + col);
        float2 u3 = *reinterpret_cast<const float2*>(hsrc + (size_t)s3 * DIM + col);
        if (BN) {
            ax += fmaxf(u0.x * sc.x + sh.x, 0.f) + fmaxf(u1.x * sc.x + sh.x, 0.f)
                + fmaxf(u2.x * sc.x + sh.x, 0.f) + fmaxf(u3.x * sc.x + sh.x, 0.f);
            ay += fmaxf(u0.y * sc.y + sh.y, 0.f) + fmaxf(u1.y * sc.y + sh.y, 0.f)
                + fmaxf(u2.y * sc.y + sh.y, 0.f) + fmaxf(u3.y * sc.y + sh.y, 0.f);
        } else {
            ax += u0.x + u1.x + u2.x + u3.x;
            ay += u0.y + u1.y + u2.y + u3.y;
        }
    }
    for (; j < end; j++) {
        int s = g_eidx[j];
        float2 u = *reinterpret_cast<const float2*>(hsrc + (size_t)s * DIM + col);
        if (BN) {
            ax += fmaxf(u.x * sc.x + sh.x, 0.f);
            ay += fmaxf(u.y * sc.y + sh.y, 0.f);
        } else {
            ax += u.x; ay += u.y;
        }
    }

    // hi/lo split -> g_as (coalesced 4B stores per lane)
    __nv_bfloat16 h0 = __float2bfloat16(ax);
    __nv_bfloat16 h1 = __float2bfloat16(ay);
    __nv_bfloat16 l0 = __float2bfloat16(ax - __bfloat162float(h0));
    __nv_bfloat16 l1 = __float2bfloat16(ay - __bfloat162float(h1));
    union { __nv_bfloat162 b; uint32_t u; } HP, LP;
    HP.b.x = h0; HP.b.y = h1; LP.b.x = l0; LP.b.y = l1;
    __nv_bfloat16* op = g_as + (size_t)node * 256 + col;
    *reinterpret_cast<uint32_t*>(op) = HP.u;
    *reinterpret_cast<uint32_t*>(op + 128) = LP.u;
}

// ---------------- fused MLP (Round-4 proven mma.sync version) ----------------
#define ASTRIDE 264
#define SMEM_BYTES (2 * 128 * ASTRIDE * 2)

__device__ __forceinline__ void mma_bf16(float d[4], const uint32_t a[4], const uint32_t b0, const uint32_t b1) {
    asm volatile(
        "mma.sync.aligned.m16n8k16.row.col.f32.bf16.bf16.f32 "
        "{%0,%1,%2,%3}, {%4,%5,%6,%7}, {%8,%9}, {%0,%1,%2,%3};\n"
        : "+f"(d[0]), "+f"(d[1]), "+f"(d[2]), "+f"(d[3])
        : "r"(a[0]), "r"(a[1]), "r"(a[2]), "r"(a[3]), "r"(b0), "r"(b1));
}

__device__ __forceinline__ void ldsm_x4(uint32_t r[4], uint32_t addr) {
    asm volatile("ldmatrix.sync.aligned.m8n8.x4.shared.b16 {%0,%1,%2,%3}, [%4];\n"
                 : "=r"(r[0]), "=r"(r[1]), "=r"(r[2]), "=r"(r[3]) : "r"(addr));
}

__device__ __forceinline__ void cpa16(uint32_t dst, const void* src) {
    asm volatile("cp.async.ca.shared.global [%0], [%1], 16;\n" :: "r"(dst), "l"(src));
}
__device__ __forceinline__ void cpa_commit_wait() {
    asm volatile("cp.async.commit_group;\n");
    asm volatile("cp.async.wait_group 0;\n" ::: "memory");
}

__device__ __forceinline__ void gemm_phase(uint32_t aAddr[4], uint32_t bAddr[2], float acc[4][4][4]) {
    const int aOffs[3] = {0, 0, 128};
    const int bOffs[3] = {0, 128, 0};
#pragma unroll
    for (int p = 0; p < 3; p++) {
        int aO = aOffs[p] * 2, bO = bOffs[p] * 2;
#pragma unroll
        for (int kk = 0; kk < 128; kk += 16) {
            uint32_t a[4][4], b[2][4];
#pragma unroll
            for (int mt = 0; mt < 4; mt++) ldsm_x4(a[mt], aAddr[mt] + aO + kk * 2);
#pragma unroll
            for (int np = 0; np < 2; np++) ldsm_x4(b[np], bAddr[np] + bO + kk * 2);
#pragma unroll
            for (int mt = 0; mt < 4; mt++)
#pragma unroll
                for (int nt = 0; nt < 4; nt++)
                    mma_bf16(acc[mt][nt], a[mt], b[nt >> 1][(nt & 1) * 2], b[nt >> 1][(nt & 1) * 2 + 1]);
        }
    }
}

__global__ __launch_bounds__(256) void mlp_kernel(int layer, const float* __restrict__ b1,
                                                  const float* __restrict__ b2, int n) {
    extern __shared__ char smem_raw[];
    __nv_bfloat16* As = reinterpret_cast<__nv_bfloat16*>(smem_raw);
    __nv_bfloat16* Bs = As + 128 * ASTRIDE;
    uint32_t sA = (uint32_t)__cvta_generic_to_shared(As);
    uint32_t sB = (uint32_t)__cvta_generic_to_shared(Bs);

    const __nv_bfloat16* __restrict__ W1g = g_wt + (size_t)(layer * 2 + 0) * 128 * 256;
    const __nv_bfloat16* __restrict__ W2g = g_wt + (size_t)(layer * 2 + 1) * 128 * 256;

    int tid = threadIdx.x;
    int rowBase = blockIdx.x * 128;

    for (int i = tid; i < 4096; i += 256) {
        int r = i >> 5, s = i & 31;
        int row = rowBase + r; if (row >= n) row = 0;
        cpa16(sA + (r * ASTRIDE + s * 8) * 2, g_as + (size_t)row * 256 + s * 8);
        cpa16(sB + (r * ASTRIDE + s * 8) * 2, W1g + (size_t)r * 256 + s * 8);
    }
    cpa_commit_wait();
    __syncthreads();

    int warp = tid >> 5, lane = tid & 31;
    int wm = warp & 1, wn = warp >> 1;
    int mBase = wm * 64, nBase = wn * 32;
    int g = lane >> 2, t = lane & 3;

    uint32_t aAddr[4], bAddr[2];
    {
        int r16 = lane & 15, half = lane >> 4;
#pragma unroll
        for (int mt = 0; mt < 4; mt++)
            aAddr[mt] = sA + ((mBase + mt * 16 + r16) * ASTRIDE + half * 8) * 2;
        int q = lane >> 3, rw = lane & 7;
        int rowoff = (q >> 1) * 8 + rw, coloff = (q & 1) * 8;
#pragma unroll
        for (int np = 0; np < 2; np++)
            bAddr[np] = sB + ((nBase + np * 16 + rowoff) * ASTRIDE + coloff) * 2;
    }

    float acc[4][4][4];
#pragma unroll
    for (int a = 0; a < 4; a++)
#pragma unroll
        for (int b = 0; b < 4; b++)
#pragma unroll
            for (int c = 0; c < 4; c++) acc[a][b][c] = 0.f;

    gemm_phase(aAddr, bAddr, acc);
    __syncthreads();

    for (int i = tid; i < 4096; i += 256) {
        int r = i >> 5, s = i & 31;
        cpa16(sB + (r * ASTRIDE + s * 8) * 2, W2g + (size_t)r * 256 + s * 8);
    }
    asm volatile("cp.async.commit_group;\n");

#pragma unroll
    for (int mt = 0; mt < 4; mt++) {
#pragma unroll
        for (int i = 0; i < 2; i++) {
            int lrow = mBase + mt * 16 + g + i * 8;
#pragma unroll
            for (int nt = 0; nt < 4; nt++) {
                int col = nBase + nt * 8 + t * 2;
                float v0 = fmaxf(acc[mt][nt][i * 2 + 0] + __ldg(b1 + col), 0.f);
                float v1 = fmaxf(acc[mt][nt][i * 2 + 1] + __ldg(b1 + col + 1), 0.f);
                __nv_bfloat16 h0 = __float2bfloat16(v0);
                __nv_bfloat16 h1 = __float2bfloat16(v1);
                __nv_bfloat16 l0 = __float2bfloat16(v0 - __bfloat162float(h0));
                __nv_bfloat16 l1 = __float2bfloat16(v1 - __bfloat162float(h1));
                __nv_bfloat162 hp; hp.x = h0; hp.y = h1;
                __nv_bfloat162 lp; lp.x = l0; lp.y = l1;
                __nv_bfloat16* op = As + lrow * ASTRIDE + col;
                *reinterpret_cast<__nv_bfloat162*>(op) = hp;
                *reinterpret_cast<__nv_bfloat162*>(op + 128) = lp;
            }
        }
    }
    asm volatile("cp.async.wait_group 0;\n" ::: "memory");
    __syncthreads();

#pragma unroll
    for (int a = 0; a < 4; a++)
#pragma unroll
        for (int b = 0; b < 4; b++)
#pragma unroll
            for (int c = 0; c < 4; c++) acc[a][b][c] = 0.f;

    gemm_phase(aAddr, bAddr, acc);

    __syncthreads();
    float* ssum = reinterpret_cast<float*>(smem_raw);
    float* ssq = ssum + 128;
    if (tid < 128) { ssum[tid] = 0.f; ssq[tid] = 0.f; }
    __syncthreads();

    float cs[4][2], cq[4][2];
#pragma unroll
    for (int nt = 0; nt < 4; nt++) { cs[nt][0] = cs[nt][1] = 0.f; cq[nt][0] = cq[nt][1] = 0.f; }
#pragma unroll
    for (int mt = 0; mt < 4; mt++) {
#pragma unroll
        for (int i = 0; i < 2; i++) {
            int row = rowBase + mBase + mt * 16 + g + i * 8;
            if (row >= n) continue;
#pragma unroll
            for (int nt = 0; nt < 4; nt++) {
                int col = nBase + nt * 8 + t * 2;
                float v0 = acc[mt][nt][i * 2 + 0] + __ldg(b2 + col);
                float v1 = acc[mt][nt][i * 2 + 1] + __ldg(b2 + col + 1);
                float2 zv; zv.x = v0; zv.y = v1;
                *reinterpret_cast<float2*>(g_z + (size_t)row * DIM + col) = zv;
                cs[nt][0] += v0; cq[nt][0] += v0 * v0;
                cs[nt][1] += v1; cq[nt][1] += v1 * v1;
            }
        }
    }
#pragma unroll
    for (int nt = 0; nt < 4; nt++) {
#pragma unroll
        for (int j = 0; j < 2; j++) {
            int col = nBase + nt * 8 + t * 2 + j;
            atomicAdd(&ssum[col], cs[nt][j]);
            atomicAdd(&ssq[col], cq[nt][j]);
        }
    }
    __syncthreads();
    if (tid < 128) {
        atomicAdd(&g_stats[tid], ssum[tid]);
        atomicAdd(&g_stats[128 + tid], ssq[tid]);
    }
}

// ---------------- stats finalize ----------------
__global__ void finalize_kernel(const float* __restrict__ gamma, const float* __restrict__ beta, int n) {
    int c = threadIdx.x;
    if (c < 128) {
        float invN = 1.f / (float)n;
        float mean = g_stats[c] * invN;
        float var = g_stats[128 + c] * invN - mean * mean;
        float rstd = rsqrtf(fmaxf(var, 0.f) + 1e-5f);
        float scale = gamma[c] * rstd;
        g_bnScale[c] = scale;
        g_bnShift[c] = beta[c] - mean * scale;
        g_stats[c] = 0.f;
        g_stats[128 + c] = 0.f;
    }
}

// ---------------- final BN+ReLU -> d_out ----------------
__global__ void bnfinal_kernel(float* __restrict__ dout, int n) {
    int idx = blockIdx.x * blockDim.x + threadIdx.x;
    if (idx >= n * 32) return;
    int row = idx >> 5;
    int c4 = (idx & 31) * 4;
    float4 z = *reinterpret_cast<const float4*>(g_z + (size_t)row * DIM + c4);
    float4 sc = *reinterpret_cast<const float4*>(g_bnScale + c4);
    float4 sh = *reinterpret_cast<const float4*>(g_bnShift + c4);
    float4 o;
    o.x = fmaxf(z.x * sc.x + sh.x, 0.f);
    o.y = fmaxf(z.y * sc.y + sh.y, 0.f);
    o.z = fmaxf(z.z * sc.z + sh.z, 0.f);
    o.w = fmaxf(z.w * sc.w + sh.w, 0.f);
    *reinterpret_cast<float4*>(dout + (size_t)row * DIM + c4) = o;
}

// ---------------- host launcher ----------------
extern "C" void kernel_launch(void* const* d_in, const int* in_sizes, int n_in,
                              void* d_out, int out_size) {
    const float* x = (const float*)d_in[0];
    const void* ei = d_in[1];
    const float* W1 = (const float*)d_in[2];
    const float* b1 = (const float*)d_in[3];
    const float* W2 = (const float*)d_in[4];
    const float* b2 = (const float*)d_in[5];
    const float* gamma = (const float*)d_in[6];
    const float* beta = (const float*)d_in[7];
    (void)n_in; (void)out_size;

    int n = in_sizes[0] / DIM;
    int E = in_sizes[1] / 2;
    if (n > NNODES) n = NNODES;
    if (E > NEDGES) E = NEDGES;

    cudaFuncSetAttribute(mlp_kernel, cudaFuncAttributeMaxDynamicSharedMemorySize, SMEM_BYTES);

    int gatherBlocks = (n * 64 + 255) / 256;   // 2 warps per node

    detect_kernel<<<1, 256>>>(ei, E, n);                               // 0
    wprep_kernel<<<(3 * 2 * 128 * 128 + 255) / 256, 256>>>(W1, W2);    // 1
    zerodeg_kernel<<<(n + 255) / 256, 256>>>(n);                       // 2
    probe_kernel<<<gatherBlocks, 256>>>(x, n);                         // 3 <- ncu capture slot
    hist_kernel<<<(E + 255) / 256, 256>>>(ei, E, n);                   // 4
    int nsb = (n + 511) / 512;
    scanA_kernel<<<nsb, 512>>>(n);
    scanB_kernel<<<1, 32>>>(nsb);
    scanC_kernel<<<nsb, 512>>>(n);
    fill_kernel<<<(E + 255) / 256, 256>>>(ei, E, n);

    int gemmBlocks = (n + 127) / 128;
    int ewBlocks = (n * 32 + 255) / 256;
    for (int l = 0; l < 3; l++) {
        if (l == 0) gather_kernel<0><<<gatherBlocks, 256>>>(x, n);
        else gather_kernel<1><<<gatherBlocks, 256>>>(nullptr, n);
        mlp_kernel<<<gemmBlocks, 256, SMEM_BYTES>>>(l, b1 + l * 128, b2 + l * 128, n);
        finalize_kernel<<<1, 128>>>(gamma + l * 128, beta + l * 128, n);
    }
    bnfinal_kernel<<<ewBlocks, 256>>>((float*)d_out, n);
}